// round 9
// baseline (speedup 1.0000x reference)
#include <cuda_runtime.h>

#define LOG2E 1.4426950408889634f
#define LN2   0.6931471805599453f
#define B    512
#define TT   1024
#define L    48
#define RING 16   // cp.async emission ring slots (512B each)

__device__ float g_fwd[B];
__device__ float g_gold[B];

static __device__ __forceinline__ float ex2f(float x){ float y; asm("ex2.approx.ftz.f32 %0, %1;" : "=f"(y) : "f"(x)); return y; }
static __device__ __forceinline__ float lg2f(float x){ float y; asm("lg2.approx.ftz.f32 %0, %1;" : "=f"(y) : "f"(x)); return y; }
static __device__ __forceinline__ unsigned smem_u32(const void* p){
    unsigned a; asm("{ .reg .u64 t; cvta.to.shared.u64 t, %1; cvt.u32.u64 %0, t; }" : "=r"(a) : "l"(p)); return a; }

// ---------------------------------------------------------------------------
// Forward kernel: 256 blocks x 96 threads (3 warps), 2 sequences per block.
// Thread (seq = tid/48, j = tid%48) runs a scalar 48-FMA dot for label j.
// Changes vs R8 (chain-bound at ~334 cyc/step):
//  - cp.async wait_group only every 4th step (count 11) — DEPBAR-class waits
//    cost O(100) cyc even when satisfied; was paid every step.
//  - 8 accumulators: FMA dep chain 48 -> 24 cyc (+12 tree).
//  - emission LDS + mask word hoisted before the dot (ex2f overlaps FMAs).
//  - explicit unroll-2: static buffer alternation, no pointer swap.
// ---------------------------------------------------------------------------
__global__ __launch_bounds__(96, 1) void crf_fwd_kernel(
    const float* __restrict__ em, const int* __restrict__ mask,
    const float* __restrict__ trans, const float* __restrict__ startt,
    const float* __restrict__ endt)
{
    __shared__ __align__(16) float sh_u0[96];          // state buffer (even t reads)
    __shared__ __align__(16) float sh_u1[96];          // state buffer (odd t writes)
    __shared__ __align__(16) float sh_em[RING][128];   // ring: [0..47]=A, [64..111]=B
    __shared__ unsigned mb[2][32];                     // mask bits per seq
    __shared__ float sc[96];

    const int tid = threadIdx.x;
    const int seq = tid >= 48;            // 0 = A, 1 = B
    const int j   = tid - seq * 48;
    const int bA  = blockIdx.x * 2;
    const int bme = bA + seq;             // this thread's batch element

    // ---- mask bits via ballot (warp 0 does both sequences) ----
    if (tid < 32) {
        #pragma unroll 1
        for (int k = 0; k < 32; k++) {
            int vA = mask[bA * TT + k * 32 + tid];
            unsigned wA = __ballot_sync(0xFFFFFFFFu, vA != 0);
            if (tid == k) mb[0][k] = wA;
            int vB = mask[(bA + 1) * TT + k * 32 + tid];
            unsigned wB = __ballot_sync(0xFFFFFFFFu, vB != 0);
            if (tid == k) mb[1][k] = wB;
        }
    }

    // ---- transition column j, exponentiated, scalar (48 regs) ----
    float et[L];
    #pragma unroll
    for (int i = 0; i < L; i++)
        et[i] = ex2f(trans[i * L + j] * LOG2E);
    const float expEnd = ex2f(endt[j] * LOG2E);

    // ---- initial state u0 = exp(start + em[0]) ----
    float res = ex2f((startt[j] + em[(size_t)bme * TT * L + j]) * LOG2E);
    sh_u0[seq * 48 + j] = res;

    // ---- cp.async producer: lanes 0..11 -> seq A, 12..23 -> seq B ----
    const float* gbase = (tid < 12) ? (em + (size_t)bA * TT * L + tid * 4)
                                    : (em + (size_t)(bA + 1) * TT * L + (tid - 12) * 4);
    const unsigned dst_off  = (tid < 12) ? (unsigned)(tid * 16) : (unsigned)(256 + (tid - 12) * 16);
    const unsigned ring_base = smem_u32(&sh_em[0][0]);

    for (int tp = 1; tp < RING; ++tp) {
        if (tid < 24) {
            const float* src = gbase + (size_t)tp * L;
            unsigned d = ring_base + (unsigned)tp * 512u + dst_off;
            asm volatile("cp.async.cg.shared.global [%0], [%1], 16;" :: "r"(d), "l"(src));
        }
        asm volatile("cp.async.commit_group;");
    }
    asm volatile("cp.async.wait_group 11;");   // rows 1..4 resident
    __syncthreads();

    int iA = 0;                                // exact integer log2 credit
    const float* prA = sh_u0 + seq * 48;       // read for odd t
    float*       pwA = sh_u1 + seq * 48;       // write for odd t

    // One simulation step: reads PR (u[t-1]), writes PW (u[t]), updates res/iA.
    #define STEP_BODY(T, PR, PW)                                               \
    do {                                                                       \
        const int t_ = (T);                                                    \
        if ((t_ & 3) == 1)                                                     \
            asm volatile("cp.async.wait_group 11;");                           \
        /* hoisted: emission + mask word (independent of u) */                 \
        const int slot_ = t_ & (RING - 1);                                     \
        float emv_ = sh_em[slot_][seq * 64 + j];                               \
        unsigned mword_ = mb[seq][t_ >> 5];                                    \
        /* 48-FMA dot, 8 accumulators */                                       \
        const float4* up_ = reinterpret_cast<const float4*>(PR);               \
        float a0=0.f,a1=0.f,a2=0.f,a3=0.f,a4=0.f,a5=0.f,a6=0.f,a7=0.f;         \
        float first_ = 0.f;                                                    \
        _Pragma("unroll")                                                      \
        for (int q = 0; q < 6; q++) {                                          \
            float4 v_ = up_[2 * q];                                            \
            float4 w_ = up_[2 * q + 1];                                        \
            if (q == 0) first_ = v_.x;                                         \
            a0 = fmaf(v_.x, et[8 * q + 0], a0);                                \
            a1 = fmaf(v_.y, et[8 * q + 1], a1);                                \
            a2 = fmaf(v_.z, et[8 * q + 2], a2);                                \
            a3 = fmaf(v_.w, et[8 * q + 3], a3);                                \
            a4 = fmaf(w_.x, et[8 * q + 4], a4);                                \
            a5 = fmaf(w_.y, et[8 * q + 5], a5);                                \
            a6 = fmaf(w_.z, et[8 * q + 6], a6);                                \
            a7 = fmaf(w_.w, et[8 * q + 7], a7);                                \
        }                                                                      \
        float dot_ = ((a0 + a1) + (a2 + a3)) + ((a4 + a5) + (a6 + a7));        \
        float Ee_  = ex2f(emv_ * LOG2E);                                       \
        float prod_ = dot_ * Ee_;                                              \
        bool mbit_ = (mword_ >> (t_ & 31)) & 1u;                               \
        float sel_ = mbit_ ? prod_ : res;                                      \
        if ((t_ & 3) == 0) {                                                   \
            unsigned eb_ = __float_as_uint(first_) & 0x7F800000u;              \
            sel_ *= __uint_as_float(0x7F000000u - eb_);                        \
            iA += (int)(eb_ >> 23) - 127;                                      \
        }                                                                      \
        res = sel_;                                                            \
        (PW)[j] = res;                                                         \
        /* refill ring slot for row t+15 (clamped) */                          \
        {                                                                      \
            int tf_ = t_ + (RING - 1); if (tf_ > TT - 1) tf_ = TT - 1;         \
            if (tid < 24) {                                                    \
                const float* src_ = gbase + (size_t)tf_ * L;                   \
                unsigned d_ = ring_base + (unsigned)((tf_ & (RING - 1)) * 512) \
                              + dst_off;                                       \
                asm volatile("cp.async.cg.shared.global [%0], [%1], 16;"       \
                             :: "r"(d_), "l"(src_));                           \
            }                                                                  \
            asm volatile("cp.async.commit_group;");                            \
        }                                                                      \
    } while (0)

    #pragma unroll 1
    for (int t = 1; t + 1 < TT; t += 2) {
        STEP_BODY(t, prA, pwA);        // odd t: read u0, write u1
        __syncthreads();
        STEP_BODY(t + 1, sh_u1 + seq * 48, sh_u0 + seq * 48);  // even t
        __syncthreads();
    }
    STEP_BODY(TT - 1, prA, pwA);       // t = 1023 (odd): read u0, write u1
    __syncthreads();
    #undef STEP_BODY

    // ---- finalize: logZ = (log2(sum_j u_j * exp(end_j)) + credit) * ln2 ----
    sc[tid] = res * expEnd;
    __syncthreads();
    if (j == 0) {                              // tid 0 (seq A) and tid 48 (seq B)
        float s = 0.f;
        #pragma unroll
        for (int q = 0; q < L; q++) s += sc[seq * 48 + q];
        g_fwd[bme] = (lg2f(s) + (float)iA) * LN2;
    }
}

// ---------------------------------------------------------------------------
// Gold score kernel: one block per batch element.
// ---------------------------------------------------------------------------
__global__ __launch_bounds__(256, 4) void crf_gold_kernel(
    const float* __restrict__ em, const int* __restrict__ labels,
    const int* __restrict__ mask, const float* __restrict__ trans,
    const float* __restrict__ startt, const float* __restrict__ endt)
{
    __shared__ float red[256];
    __shared__ int   redc[256];
    const int b = blockIdx.x;
    const int tid = threadIdx.x;

    float acc = 0.f;
    int cnt = 0;
    for (int t = tid; t < TT; t += 256) {
        int l = labels[b * TT + t];
        int m = mask[b * TT + t];
        cnt += m;
        float e = em[((size_t)(b * TT) + t) * L + l];
        if (t == 0) {
            acc += startt[l] + e;
        } else {
            int lp = labels[b * TT + t - 1];
            acc += (e + trans[l * L + lp]) * (float)m;
        }
    }
    red[tid] = acc; redc[tid] = cnt;
    __syncthreads();
    for (int s = 128; s > 0; s >>= 1) {
        if (tid < s) { red[tid] += red[tid + s]; redc[tid] += redc[tid + s]; }
        __syncthreads();
    }
    if (tid == 0) {
        int len = redc[0] - 1;
        int last = labels[b * TT + len];
        g_gold[b] = red[0] + endt[last];
    }
}

// ---------------------------------------------------------------------------
// Final reduction: mean(fwd - gold)
// ---------------------------------------------------------------------------
__global__ __launch_bounds__(512, 1) void crf_final_kernel(float* __restrict__ out)
{
    __shared__ float red[512];
    int tid = threadIdx.x;
    red[tid] = g_fwd[tid] - g_gold[tid];
    __syncthreads();
    for (int s = 256; s > 0; s >>= 1) {
        if (tid < s) red[tid] += red[tid + s];
        __syncthreads();
    }
    if (tid == 0) out[0] = red[0] * (1.0f / (float)B);
}

extern "C" void kernel_launch(void* const* d_in, const int* in_sizes, int n_in,
                              void* d_out, int out_size)
{
    const float* em     = (const float*)d_in[0];
    const int*   labels = (const int*)  d_in[1];
    const int*   mask   = (const int*)  d_in[2];
    const float* trans  = (const float*)d_in[3];
    const float* startt = (const float*)d_in[4];
    const float* endt   = (const float*)d_in[5];
    float* out = (float*)d_out;

    crf_fwd_kernel<<<B / 2, 96>>>(em, mask, trans, startt, endt);
    crf_gold_kernel<<<B, 256>>>(em, labels, mask, trans, startt, endt);
    crf_final_kernel<<<1, 512>>>(out);
}